// round 10
// baseline (speedup 1.0000x reference)
#include <cuda_runtime.h>
#include <cstdint>

// KernelRepeatLinear: out[b,e,j] = bias[j] + sum_k weight[k,j] * P[b, e-7+k, j]
// P[b,e,j] = sum_{i<=j} x[b,e,i] * dv^(j-i)   (decayed inclusive prefix scan over dim)
#define Bv 8
#define Ev 2048
#define Sv 512
#define Kv 8
#define HALO (Kv - 1)
#define TE 32                 // output E-rows per block
#define ROWS (TE + HALO)      // 39 scanned rows (contiguous in gmem)
#define THREADS 512
#define SMEM_BYTES (ROWS * Sv * 4 + 16)

// packed fp32x2 FMA (Blackwell)
#define FMA_F32X2(d, a, b, c) \
    asm("fma.rn.f32x2 %0, %1, %2, %3;" : "=l"(d) : "l"(a), "l"(b), "l"(c))

__global__ __launch_bounds__(THREADS, 2)
void krl_fused10(const float* __restrict__ x,
                 const float* __restrict__ weight,
                 const float* __restrict__ bias,
                 const float* __restrict__ decay,
                 float* __restrict__ out)
{
    extern __shared__ __align__(16) float smem[];
    float* shP = smem;                                    // ROWS*Sv floats
    unsigned long long* mbarp = (unsigned long long*)(smem + ROWS * Sv);

    const int tid  = threadIdx.x;
    const int lane = tid & 31;
    const int warp = tid >> 5;         // 0..15

    const int blocksPerBatch = Ev / TE;           // 64
    const int b  = blockIdx.x / blocksPerBatch;
    const int t  = blockIdx.x % blocksPerBatch;
    const int e0 = t * TE;

    const float* xb = x + (size_t)b * Ev * Sv;

    uint32_t mbar_addr, shP_addr;
    {
        uint64_t tmp;
        asm("cvta.to.shared.u64 %0, %1;" : "=l"(tmp) : "l"(mbarp));
        mbar_addr = (uint32_t)tmp;
        asm("cvta.to.shared.u64 %0, %1;" : "=l"(tmp) : "l"(shP));
        shP_addr = (uint32_t)tmp;
    }

    if (tid == 0)
        asm volatile("mbarrier.init.shared.b64 [%0], %1;" :: "r"(mbar_addr), "r"(1) : "memory");
    __syncthreads();

    const int gFirstWanted = e0 - HALO;
    const int gFirst       = gFirstWanted < 0 ? 0 : gFirstWanted;
    const int dstRow       = gFirst - gFirstWanted;     // 0, or 7 when t==0
    const int nRows        = (e0 + TE) - gFirst;        // 39, or 32 when t==0
    const uint32_t bytes   = (uint32_t)nRows * Sv * 4u;

    if (tid == 0) {
        asm volatile("mbarrier.arrive.expect_tx.shared.b64 _, [%0], %1;"
                     :: "r"(mbar_addr), "r"(bytes) : "memory");
        asm volatile("cp.async.bulk.shared::cta.global.mbarrier::complete_tx::bytes "
                     "[%0], [%1], %2, [%3];"
                     :: "r"(shP_addr + (uint32_t)dstRow * Sv * 4u),
                        "l"(xb + (size_t)gFirst * Sv),
                        "r"(bytes), "r"(mbar_addr) : "memory");
    }

    if (dstRow != 0) {                               // zero halo (first tile only)
        float4* z = (float4*)shP;
        for (int i = tid; i < dstRow * (Sv / 4); i += THREADS)
            z[i] = make_float4(0.f, 0.f, 0.f, 0.f);
    }

    float dv = decay[1];
    dv = fminf(1.0f, fmaxf(0.9f, dv));
    const float dv2 = dv * dv;
    const float dv3 = dv2 * dv;
    const float dv4 = dv2 * dv2;
    const float dv8 = dv4 * dv4;
    const float dv16 = dv8 * dv8;

    // hoist weight/bias LDGs: latency hides behind the TMA wait
    const int jq = tid & 255;                         // float2 column, 0..255
    const int gsel = tid >> 8;                        // 0/1: output-group parity
    unsigned long long wv[Kv];
    #pragma unroll
    for (int k = 0; k < Kv; ++k)
        wv[k] = ((const unsigned long long*)(weight + k * Sv))[jq];
    const unsigned long long bv = ((const unsigned long long*)bias)[jq];

    // ---- wait for the TMA tile ----
    {
        uint32_t done;
        asm volatile(
            "{\n\t.reg .pred p;\n\t"
            "mbarrier.try_wait.parity.acquire.cta.shared::cta.b64 p, [%1], %2;\n\t"
            "selp.b32 %0, 1, 0, p;\n\t}"
            : "=r"(done) : "r"(mbar_addr), "r"(0) : "memory");
        if (!done) {
            asm volatile(
                "{\n\t.reg .pred P1;\n\t"
                "WAIT_LOOP_%=:\n\t"
                "mbarrier.try_wait.parity.acquire.cta.shared::cta.b64 P1, [%0], %1, 0x989680;\n\t"
                "@P1 bra.uni WAIT_DONE_%=;\n\t"
                "bra.uni WAIT_LOOP_%=;\n\t"
                "WAIT_DONE_%=:\n\t}"
                :: "r"(mbar_addr), "r"(0) : "memory");
        }
    }
    __syncthreads();

    // -------- Phase 1: in-place decayed prefix scan (2-level intra-lane) ------
    for (int r = warp; r < ROWS; r += 16) {
        float4* rowp = (float4*)(shP + r * Sv);
        float4 a[4];
        #pragma unroll
        for (int q = 0; q < 4; ++q) a[q] = rowp[4 * lane + q];

        // Step A: 4 independent depth-3 intra-group scans
        #pragma unroll
        for (int q = 0; q < 4; ++q) {
            a[q].y = fmaf(dv, a[q].x, a[q].y);
            a[q].z = fmaf(dv, a[q].y, a[q].z);
            a[q].w = fmaf(dv, a[q].z, a[q].w);
        }
        // Step B: scan group totals with factor dv^4
        const float S0 = a[0].w;
        const float S1 = fmaf(dv4, S0, a[1].w);
        const float S2 = fmaf(dv4, S1, a[2].w);
        const float S3 = fmaf(dv4, S2, a[3].w);
        // Step C: add carries into groups 1..3 (independent FMAs)
        a[1].x = fmaf(S0, dv,  a[1].x);
        a[1].y = fmaf(S0, dv2, a[1].y);
        a[1].z = fmaf(S0, dv3, a[1].z);
        a[1].w = S1;
        a[2].x = fmaf(S1, dv,  a[2].x);
        a[2].y = fmaf(S1, dv2, a[2].y);
        a[2].z = fmaf(S1, dv3, a[2].z);
        a[2].w = S2;
        a[3].x = fmaf(S2, dv,  a[3].x);
        a[3].y = fmaf(S2, dv2, a[3].y);
        a[3].z = fmaf(S2, dv3, a[3].z);
        a[3].w = S3;

        // Kogge-Stone inclusive warp scan of segment ends, hop factor dv^16
        float s = S3;
        float f = dv16;
        #pragma unroll
        for (int d = 1; d < 32; d <<= 1) {
            float o = __shfl_up_sync(0xffffffffu, s, d);
            if (lane >= d) s = fmaf(f, o, s);
            f = f * f;
        }
        float carry = __shfl_up_sync(0xffffffffu, s, 1);
        if (lane == 0) carry = 0.f;

        float cq = carry * dv;                        // carry * dv^(4q+1)
        #pragma unroll
        for (int q = 0; q < 4; ++q) {
            a[q].x = a[q].x + cq;
            a[q].y = fmaf(cq, dv,  a[q].y);
            a[q].z = fmaf(cq, dv2, a[q].z);
            a[q].w = fmaf(cq, dv3, a[q].w);
            rowp[4 * lane + q] = a[q];
            cq = cq * dv4;
        }
    }
    __syncthreads();

    // -------- Phase 2: scatter-form FIR, 8 independent accumulators ----------
    // thread (jq, gsel) handles output-groups {gsel, gsel+2} (8 rows each);
    // group G uses scan rows [8G, 8G+15), outputs rows [8G, 8G+8).
    unsigned long long* outp =
        (unsigned long long*)(out + ((size_t)b * Ev + e0) * Sv);

    #pragma unroll
    for (int gi = 0; gi < 2; ++gi) {
        const int rb = (gsel + 2 * gi) * 8;
        unsigned long long acc[8];
        #pragma unroll
        for (int o = 0; o < 8; ++o) acc[o] = bv;

        unsigned long long vcur =
            ((const unsigned long long*)(shP + rb * Sv))[jq];
        #pragma unroll
        for (int i = 0; i < 15; ++i) {
            unsigned long long vnext = 0ull;
            if (i < 14)
                vnext = ((const unsigned long long*)(shP + (rb + i + 1) * Sv))[jq];
            #pragma unroll
            for (int k = 0; k < 8; ++k) {
                if (i - k >= 0 && i - k < 8)
                    FMA_F32X2(acc[i - k], wv[k], vcur, acc[i - k]);
            }
            vcur = vnext;
        }
        #pragma unroll
        for (int o = 0; o < 8; ++o)
            outp[(size_t)(rb + o) * (Sv / 2) + jq] = acc[o];
    }
}

extern "C" void kernel_launch(void* const* d_in, const int* in_sizes, int n_in,
                              void* d_out, int out_size)
{
    const float* x      = (const float*)d_in[0];  // (B, E, S)
    const float* weight = (const float*)d_in[1];  // (K, S)
    const float* bias   = (const float*)d_in[2];  // (S,)
    const float* decay  = (const float*)d_in[3];  // (2, 1)
    float* out          = (float*)d_out;          // (B, E, S)

    cudaFuncSetAttribute(krl_fused10,
                         cudaFuncAttributeMaxDynamicSharedMemorySize, SMEM_BYTES);
    krl_fused10<<<Bv * (Ev / TE), THREADS, SMEM_BYTES>>>(x, weight, bias, decay, out);
}

// round 11
// speedup vs baseline: 1.1447x; 1.1447x over previous
#include <cuda_runtime.h>
#include <cstdint>

// KernelRepeatLinear: out[b,e,j] = bias[j] + sum_k weight[k,j] * P[b, e-7+k, j]
// P[b,e,j] = sum_{i<=j} x[b,e,i] * dv^(j-i)   (decayed inclusive prefix scan over dim)
#define Bv 8
#define Ev 2048
#define Sv 512
#define Kv 8
#define HALO (Kv - 1)
#define TE 16
#define ROWS (TE + HALO)      // 23 scanned rows (contiguous in gmem)
#define THREADS 256

typedef unsigned long long u64;

// packed fp32x2 ops (Blackwell)
#define FMA_F32X2(d, a, b, c) \
    asm("fma.rn.f32x2 %0, %1, %2, %3;" : "=l"(d) : "l"(a), "l"(b), "l"(c))
#define PACK_F32X2(out, lo, hi) \
    asm("mov.b64 %0, {%1, %2};" : "=l"(out) : "f"(lo), "f"(hi))
#define UNPACK_F32X2(lo, hi, in) \
    asm("mov.b64 {%0, %1}, %2;" : "=f"(lo), "=f"(hi) : "l"(in))

__global__ __launch_bounds__(THREADS, 4)
void krl_fused11(const float* __restrict__ x,
                 const float* __restrict__ weight,
                 const float* __restrict__ bias,
                 const float* __restrict__ decay,
                 float* __restrict__ out)
{
    __shared__ float shP[ROWS * Sv];                 // 47104 B
    __shared__ __align__(8) u64 mbar;

    const int tid  = threadIdx.x;
    const int lane = tid & 31;
    const int warp = tid >> 5;

    const int blocksPerBatch = Ev / TE;              // 128
    const int b  = blockIdx.x / blocksPerBatch;
    const int t  = blockIdx.x % blocksPerBatch;
    const int e0 = t * TE;

    const float* xb = x + (size_t)b * Ev * Sv;

    uint32_t mbar_addr, shP_addr;
    {
        uint64_t tmp;
        asm("cvta.to.shared.u64 %0, %1;" : "=l"(tmp) : "l"(&mbar));
        mbar_addr = (uint32_t)tmp;
        asm("cvta.to.shared.u64 %0, %1;" : "=l"(tmp) : "l"(shP));
        shP_addr = (uint32_t)tmp;
    }

    if (tid == 0)
        asm volatile("mbarrier.init.shared.b64 [%0], %1;" :: "r"(mbar_addr), "r"(1) : "memory");
    __syncthreads();

    const int gFirstWanted = e0 - HALO;
    const int gFirst       = gFirstWanted < 0 ? 0 : gFirstWanted;
    const int dstRow       = gFirst - gFirstWanted;  // 0, or 7 on first tile
    const int nRows        = (e0 + TE) - gFirst;
    const uint32_t bytes   = (uint32_t)nRows * Sv * 4u;

    if (tid == 0) {
        asm volatile("mbarrier.arrive.expect_tx.shared.b64 _, [%0], %1;"
                     :: "r"(mbar_addr), "r"(bytes) : "memory");
        asm volatile("cp.async.bulk.shared::cta.global.mbarrier::complete_tx::bytes "
                     "[%0], [%1], %2, [%3];"
                     :: "r"(shP_addr + (uint32_t)dstRow * Sv * 4u),
                        "l"(xb + (size_t)gFirst * Sv),
                        "r"(bytes), "r"(mbar_addr) : "memory");
    }

    if (dstRow != 0) {                                // zero halo (first tile only)
        float4* z = (float4*)shP;
        for (int i = tid; i < dstRow * (Sv / 4); i += THREADS)
            z[i] = make_float4(0.f, 0.f, 0.f, 0.f);
    }

    float dv = decay[1];
    dv = fminf(1.0f, fmaxf(0.9f, dv));
    const float dv2 = dv * dv;
    const float dv4 = dv2 * dv2;
    const float dv8 = dv4 * dv4;
    const float dv16 = dv8 * dv8;

    // packed constants
    u64 dvP, dv2P;
    PACK_F32X2(dvP,  dv,  dv);
    PACK_F32X2(dv2P, dv2, dv2);
    // D[m] = (dv^(2m+1), dv^(2m+2)) for the carry apply
    u64 D[8];
    {
        float pw = dv;                                // dv^1
        #pragma unroll
        for (int m = 0; m < 8; ++m) {
            float lo = pw, hi = pw * dv;              // dv^(2m+1), dv^(2m+2)
            PACK_F32X2(D[m], lo, hi);
            pw = hi * dv;
        }
    }

    // hoist weight/bias LDGs: latency hides behind the TMA wait
    const int jq = tid;                               // float2 column, 0..255
    u64 wv[Kv];
    #pragma unroll
    for (int k = 0; k < Kv; ++k)
        wv[k] = ((const u64*)(weight + k * Sv))[jq];
    const u64 bv = ((const u64*)bias)[jq];

    // ---- wait for the TMA tile ----
    {
        uint32_t done;
        asm volatile(
            "{\n\t.reg .pred p;\n\t"
            "mbarrier.try_wait.parity.acquire.cta.shared::cta.b64 p, [%1], %2;\n\t"
            "selp.b32 %0, 1, 0, p;\n\t}"
            : "=r"(done) : "r"(mbar_addr), "r"(0) : "memory");
        if (!done) {
            asm volatile(
                "{\n\t.reg .pred P1;\n\t"
                "WAIT_LOOP_%=:\n\t"
                "mbarrier.try_wait.parity.acquire.cta.shared::cta.b64 P1, [%0], %1, 0x989680;\n\t"
                "@P1 bra.uni WAIT_DONE_%=;\n\t"
                "bra.uni WAIT_LOOP_%=;\n\t"
                "WAIT_DONE_%=:\n\t}"
                :: "r"(mbar_addr), "r"(0) : "memory");
        }
    }
    __syncthreads();

    // -------- Phase 1: packed even/odd decayed prefix scan, in place ----------
    // v_i = x_i + dv*x_{i-1};  p_i = dv^2 * p_{i-2} + v_i  (both parities packed)
    for (int r = warp; r < ROWS; r += 8) {
        ulonglong2* rp = (ulonglong2*)(shP + r * Sv);
        u64 P[8];                                     // P[m] = (f_{2m}, f_{2m+1})
        #pragma unroll
        for (int q = 0; q < 4; ++q) {
            ulonglong2 L = rp[4 * lane + q];
            P[2 * q]     = L.x;
            P[2 * q + 1] = L.y;
        }
        // build V in place (descending so P[m-1] is still original)
        #pragma unroll
        for (int m = 7; m >= 0; --m) {
            float plo, phi, prevhi;
            UNPACK_F32X2(plo, phi, P[m]);
            if (m > 0) {
                float dlo, dhi;
                UNPACK_F32X2(dlo, dhi, P[m - 1]);
                prevhi = dhi;
            } else {
                prevhi = 0.f;
            }
            u64 Q;
            PACK_F32X2(Q, prevhi, plo);               // (f_{2m-1}, f_{2m})
            FMA_F32X2(P[m], dvP, Q, P[m]);            // V_m
        }
        // packed scan: S_m = dv2 * S_{m-1} + V_m   (S overwrites V in P[])
        #pragma unroll
        for (int m = 1; m < 8; ++m)
            FMA_F32X2(P[m], dv2P, P[m - 1], P[m]);

        // segment end p_15 = hi(P[7])
        float s_lo, s;
        UNPACK_F32X2(s_lo, s, P[7]);

        // Kogge-Stone inclusive warp scan of segment ends, hop factor dv^16
        float f = dv16;
        #pragma unroll
        for (int d = 1; d < 32; d <<= 1) {
            float o = __shfl_up_sync(0xffffffffu, s, d);
            if (lane >= d) s = fmaf(f, o, s);
            f = f * f;
        }
        float carry = __shfl_up_sync(0xffffffffu, s, 1);
        if (lane == 0) carry = 0.f;

        // packed carry apply: P[m] += (c,c) * (dv^(2m+1), dv^(2m+2))
        u64 c2;
        PACK_F32X2(c2, carry, carry);
        #pragma unroll
        for (int m = 0; m < 8; ++m)
            FMA_F32X2(P[m], c2, D[m], P[m]);

        #pragma unroll
        for (int q = 0; q < 4; ++q) {
            ulonglong2 Sv2;
            Sv2.x = P[2 * q];
            Sv2.y = P[2 * q + 1];
            rp[4 * lane + q] = Sv2;
        }
    }
    __syncthreads();

    // -------- Phase 2: scatter-form FIR, 8 independent accumulators ----------
    u64* outp = (u64*)(out + ((size_t)b * Ev + e0) * Sv);

    #pragma unroll
    for (int g2 = 0; g2 < 2; ++g2) {
        const int rb = g2 * 8;
        u64 acc[8];
        #pragma unroll
        for (int o = 0; o < 8; ++o) acc[o] = bv;

        u64 vcur = ((const u64*)(shP + rb * Sv))[jq];
        #pragma unroll
        for (int i = 0; i < 15; ++i) {
            u64 vnext = 0ull;
            if (i < 14)
                vnext = ((const u64*)(shP + (rb + i + 1) * Sv))[jq];
            #pragma unroll
            for (int k = 0; k < 8; ++k) {
                if (i - k >= 0 && i - k < 8)
                    FMA_F32X2(acc[i - k], wv[k], vcur, acc[i - k]);
            }
            vcur = vnext;
        }
        #pragma unroll
        for (int o = 0; o < 8; ++o)
            outp[(size_t)(rb + o) * (Sv / 2) + jq] = acc[o];
    }
}

extern "C" void kernel_launch(void* const* d_in, const int* in_sizes, int n_in,
                              void* d_out, int out_size)
{
    const float* x      = (const float*)d_in[0];  // (B, E, S)
    const float* weight = (const float*)d_in[1];  // (K, S)
    const float* bias   = (const float*)d_in[2];  // (S,)
    const float* decay  = (const float*)d_in[3];  // (2, 1)
    float* out          = (float*)d_out;          // (B, E, S)

    krl_fused11<<<Bv * (Ev / TE), THREADS>>>(x, weight, bias, decay, out);
}

// round 12
// speedup vs baseline: 1.2076x; 1.0550x over previous
#include <cuda_runtime.h>
#include <cstdint>

// KernelRepeatLinear: out[b,e,j] = bias[j] + sum_k weight[k,j] * P[b, e-7+k, j]
// P[b,e,j] = sum_{i<=j} x[b,e,i] * dv^(j-i)   (decayed inclusive prefix scan over dim)
#define Bv 8
#define Ev 2048
#define Sv 512
#define Kv 8
#define HALO (Kv - 1)
#define TE 16
#define ROWS (TE + HALO)      // 23 scanned rows (contiguous in gmem)
#define THREADS 256

typedef unsigned long long u64;

// packed fp32x2 FMA (Blackwell)
#define FMA_F32X2(d, a, b, c) \
    asm("fma.rn.f32x2 %0, %1, %2, %3;" : "=l"(d) : "l"(a), "l"(b), "l"(c))

__global__ __launch_bounds__(THREADS, 4)
void krl_fused12(const float* __restrict__ x,
                 const float* __restrict__ weight,
                 const float* __restrict__ bias,
                 const float* __restrict__ decay,
                 float* __restrict__ out)
{
    __shared__ float shP[ROWS * Sv];                 // 47104 B (x, then P in place)
    __shared__ __align__(8) u64 mbar;

    const int tid  = threadIdx.x;
    const int lane = tid & 31;
    const int warp = tid >> 5;

    const int blocksPerBatch = Ev / TE;              // 128
    const int b  = blockIdx.x / blocksPerBatch;
    const int t  = blockIdx.x % blocksPerBatch;
    const int e0 = t * TE;

    const float* xb = x + (size_t)b * Ev * Sv;

    uint32_t mbar_addr, shP_addr;
    {
        uint64_t tmp;
        asm("cvta.to.shared.u64 %0, %1;" : "=l"(tmp) : "l"(&mbar));
        mbar_addr = (uint32_t)tmp;
        asm("cvta.to.shared.u64 %0, %1;" : "=l"(tmp) : "l"(shP));
        shP_addr = (uint32_t)tmp;
    }

    if (tid == 0)
        asm volatile("mbarrier.init.shared.b64 [%0], %1;" :: "r"(mbar_addr), "r"(1) : "memory");
    __syncthreads();

    const int gFirstWanted = e0 - HALO;
    const int gFirst       = gFirstWanted < 0 ? 0 : gFirstWanted;
    const int dstRow       = gFirst - gFirstWanted;  // 0, or 7 on first tile
    const int nRows        = (e0 + TE) - gFirst;
    const uint32_t bytes   = (uint32_t)nRows * Sv * 4u;

    if (tid == 0) {
        asm volatile("mbarrier.arrive.expect_tx.shared.b64 _, [%0], %1;"
                     :: "r"(mbar_addr), "r"(bytes) : "memory");
        asm volatile("cp.async.bulk.shared::cta.global.mbarrier::complete_tx::bytes "
                     "[%0], [%1], %2, [%3];"
                     :: "r"(shP_addr + (uint32_t)dstRow * Sv * 4u),
                        "l"(xb + (size_t)gFirst * Sv),
                        "r"(bytes), "r"(mbar_addr) : "memory");
    }

    if (dstRow != 0) {                                // zero halo (first tile only)
        float4* z = (float4*)shP;
        for (int i = tid; i < dstRow * (Sv / 4); i += THREADS)
            z[i] = make_float4(0.f, 0.f, 0.f, 0.f);
    }

    float dv = decay[1];
    dv = fminf(1.0f, fmaxf(0.9f, dv));
    const float dv2 = dv * dv;
    const float dv3 = dv2 * dv;
    const float dv4 = dv2 * dv2;
    const float dv8 = dv4 * dv4;
    const float dv16 = dv8 * dv8;

    // hoist weight/bias LDGs: latency hides behind the TMA wait
    const int jq = tid;                               // float2 column, 0..255
    u64 wv[Kv];
    #pragma unroll
    for (int k = 0; k < Kv; ++k)
        wv[k] = ((const u64*)(weight + k * Sv))[jq];
    const u64 bv = ((const u64*)bias)[jq];

    // ---- only warp 0 waits on the TMA barrier; others park at bar.sync ----
    if (warp == 0) {
        uint32_t done;
        asm volatile(
            "{\n\t.reg .pred p;\n\t"
            "mbarrier.try_wait.parity.acquire.cta.shared::cta.b64 p, [%1], %2;\n\t"
            "selp.b32 %0, 1, 0, p;\n\t}"
            : "=r"(done) : "r"(mbar_addr), "r"(0) : "memory");
        if (!done) {
            asm volatile(
                "{\n\t.reg .pred P1;\n\t"
                "WAIT_LOOP_%=:\n\t"
                "mbarrier.try_wait.parity.acquire.cta.shared::cta.b64 P1, [%0], %1, 0x989680;\n\t"
                "@P1 bra.uni WAIT_DONE_%=;\n\t"
                "bra.uni WAIT_LOOP_%=;\n\t"
                "WAIT_DONE_%=:\n\t}"
                :: "r"(mbar_addr), "r"(0) : "memory");
        }
    }
    __syncthreads();   // releases TMA'd data (+halo zeros) to all warps

    // -------- Phase 1: in-place decayed prefix scan (LDS -> regs -> STS) ------
    for (int r = warp; r < ROWS; r += 8) {
        float4* rowp = (float4*)(shP + r * Sv);
        float4 a[4];
        #pragma unroll
        for (int q = 0; q < 4; ++q) a[q] = rowp[4 * lane + q];

        float p = 0.f;
        #pragma unroll
        for (int q = 0; q < 4; ++q) {
            p = fmaf(dv, p, a[q].x); a[q].x = p;
            p = fmaf(dv, p, a[q].y); a[q].y = p;
            p = fmaf(dv, p, a[q].z); a[q].z = p;
            p = fmaf(dv, p, a[q].w); a[q].w = p;
        }
        float s = p;
        float f = dv16;
        #pragma unroll
        for (int d = 1; d < 32; d <<= 1) {
            float o = __shfl_up_sync(0xffffffffu, s, d);
            if (lane >= d) s = fmaf(f, o, s);
            f = f * f;
        }
        float carry = __shfl_up_sync(0xffffffffu, s, 1);
        if (lane == 0) carry = 0.f;

        float cq = carry * dv;                        // carry * dv^(4q+1)
        #pragma unroll
        for (int q = 0; q < 4; ++q) {
            a[q].x = a[q].x + cq;
            a[q].y = fmaf(cq, dv,  a[q].y);
            a[q].z = fmaf(cq, dv2, a[q].z);
            a[q].w = fmaf(cq, dv3, a[q].w);
            rowp[4 * lane + q] = a[q];
            cq = cq * dv4;
        }
    }
    __syncthreads();

    // -------- Phase 2: rolling scatter FIR, 8 rotating independent accs -------
    // out row o (0..15) = bias + sum_k wv[k] * scanrow[o+k];
    // scan row i feeds acc slot (i-k)&7 for valid k; after row i (i>=7),
    // out row i-7 is complete -> store it, recycle its slot with bv.
    u64* outp = (u64*)(out + ((size_t)b * Ev + e0) * Sv);

    u64 acc[8];
    #pragma unroll
    for (int o = 0; o < 8; ++o) acc[o] = bv;

    u64 vcur = ((const u64*)shP)[jq];
    #pragma unroll
    for (int i = 0; i < ROWS; ++i) {
        u64 vnext = 0ull;
        if (i < ROWS - 1)
            vnext = ((const u64*)(shP + (i + 1) * Sv))[jq];
        // contributions of scan row i: k in [max(0,i-15), min(7,i)]
        #pragma unroll
        for (int k = 0; k < 8; ++k) {
            const int o = i - k;
            if (o >= 0 && o < TE)
                FMA_F32X2(acc[o & 7], wv[k], vcur, acc[o & 7]);
        }
        if (i >= HALO) {                       // out row (i-7) complete
            const int o = i - HALO;
            outp[(size_t)o * (Sv / 2) + jq] = acc[o & 7];
            acc[o & 7] = bv;                   // recycle for out row o+8
        }
        vcur = vnext;
    }
}

extern "C" void kernel_launch(void* const* d_in, const int* in_sizes, int n_in,
                              void* d_out, int out_size)
{
    const float* x      = (const float*)d_in[0];  // (B, E, S)
    const float* weight = (const float*)d_in[1];  // (K, S)
    const float* bias   = (const float*)d_in[2];  // (S,)
    const float* decay  = (const float*)d_in[3];  // (2, 1)
    float* out          = (float*)d_out;          // (B, E, S)

    krl_fused12<<<Bv * (Ev / TE), THREADS>>>(x, weight, bias, decay, out);
}